// round 3
// baseline (speedup 1.0000x reference)
#include <cuda_runtime.h>

#define N_NODES 50000
#define N_EDGES 800000
#define N_GRAPHS 512
#define F_IN 128
#define HID 256

// ---------------- scratch (device globals: no allocation allowed) ----------------
__device__ int   g_is64;                              // 1 if index inputs are int64
__device__ int   g_src[N_EDGES];
__device__ int   g_dst[N_EDGES];
__device__ int   g_batch[N_NODES];
__device__ float g_dis[N_NODES];                      // deg_inv_sqrt
__device__ float g_bufA[(size_t)N_NODES * HID];       // hw  (linear output)
__device__ float g_bufB[(size_t)N_NODES * HID];       // agg / layer output
__device__ float g_pool[N_GRAPHS * HID];
__device__ float g_cnt[N_GRAPHS];

// ---------------- index dtype detection + normalization ----------------
// If edge_index is truly int64 (little-endian, values < 2^31), every odd 32-bit
// word of the raw buffer is 0. For int32 data the odd words are random node ids.
__global__ void detect_dtype(const unsigned int* __restrict__ raw) {
    if (threadIdx.x == 0) {
        int all_zero = 1;
        for (int i = 0; i < 128; i++)
            if (raw[2 * i + 1] != 0u) { all_zero = 0; break; }
        g_is64 = all_zero;
    }
}

__global__ void convert_edges(const void* __restrict__ raw) {
    int i = blockIdx.x * blockDim.x + threadIdx.x;
    if (i >= N_EDGES) return;
    if (g_is64) {
        const long long* p = (const long long*)raw;
        g_src[i] = (int)p[i];
        g_dst[i] = (int)p[i + N_EDGES];
    } else {
        const int* p = (const int*)raw;
        g_src[i] = p[i];
        g_dst[i] = p[i + N_EDGES];
    }
}

__global__ void convert_batch(const void* __restrict__ raw) {
    int i = blockIdx.x * blockDim.x + threadIdx.x;
    if (i >= N_NODES) return;
    if (g_is64) g_batch[i] = (int)((const long long*)raw)[i];
    else        g_batch[i] = ((const int*)raw)[i];
}

// ---------------- small utility kernels ----------------
__global__ void zero_dis() {
    int i = blockIdx.x * blockDim.x + threadIdx.x;
    if (i < N_NODES) g_dis[i] = 0.f;
}

__global__ void zero_pool() {
    int i = blockIdx.x * blockDim.x + threadIdx.x;
    if (i < N_GRAPHS * HID) g_pool[i] = 0.f;
    if (i < N_GRAPHS) g_cnt[i] = 0.f;
}

__global__ void deg_count() {
    int i = blockIdx.x * blockDim.x + threadIdx.x;
    if (i < N_EDGES) atomicAdd(&g_dis[g_dst[i]], 1.f);
}

__global__ void deg_fin() {
    int i = blockIdx.x * blockDim.x + threadIdx.x;
    if (i < N_NODES) g_dis[i] = rsqrtf(g_dis[i] + 1.f);
}

// ---------------- fp32 tiled GEMM: g_bufA[M,N] = A[M,K] @ W[K,N] ----------------
// BM=128, BN=64, BK=16, 256 threads, 8x4 per-thread microtile.
template <bool FROM_BUF>
__global__ void sgemm_kernel(const float* __restrict__ Aext,
                             const float* __restrict__ W,
                             int M, int K, int N) {
    const int BM = 128, BN = 64, BK = 16;
    __shared__ float As[BK][BM + 4];
    __shared__ float Bs[BK][BN];

    const float* A = FROM_BUF ? (const float*)g_bufB : Aext;
    float* C = g_bufA;

    int bm = blockIdx.y * BM;
    int bn = blockIdx.x * BN;
    int tid = threadIdx.x;
    int tr = tid >> 4;   // 0..15 -> rows tr*8..tr*8+7
    int tc = tid & 15;   // 0..15 -> cols tc*4..tc*4+3

    float acc[8][4];
#pragma unroll
    for (int m = 0; m < 8; m++)
#pragma unroll
        for (int n = 0; n < 4; n++) acc[m][n] = 0.f;

    for (int k0 = 0; k0 < K; k0 += BK) {
        // A tile: 128 rows x 16 k = 512 float4 loads (2 per thread)
        for (int i = tid; i < 512; i += 256) {
            int r = i >> 2, c4 = i & 3;
            int gr = bm + r;
            float4 v = make_float4(0.f, 0.f, 0.f, 0.f);
            if (gr < M) v = *(const float4*)(A + (size_t)gr * K + k0 + c4 * 4);
            As[c4 * 4 + 0][r] = v.x;
            As[c4 * 4 + 1][r] = v.y;
            As[c4 * 4 + 2][r] = v.z;
            As[c4 * 4 + 3][r] = v.w;
        }
        // B tile: 16 k x 64 n = 256 float4 (1 per thread)
        {
            int k = tid >> 4, n4 = tid & 15;
            float4 v = *(const float4*)(W + (size_t)(k0 + k) * N + bn + n4 * 4);
            *(float4*)&Bs[k][n4 * 4] = v;
        }
        __syncthreads();

#pragma unroll
        for (int k = 0; k < BK; k++) {
            float a[8], b[4];
#pragma unroll
            for (int m = 0; m < 8; m++) a[m] = As[k][tr * 8 + m];
#pragma unroll
            for (int n = 0; n < 4; n++) b[n] = Bs[k][tc * 4 + n];
#pragma unroll
            for (int m = 0; m < 8; m++)
#pragma unroll
                for (int n = 0; n < 4; n++) acc[m][n] = fmaf(a[m], b[n], acc[m][n]);
        }
        __syncthreads();
    }

#pragma unroll
    for (int m = 0; m < 8; m++) {
        int gr = bm + tr * 8 + m;
        if (gr < M) {
            float4 v = make_float4(acc[m][0], acc[m][1], acc[m][2], acc[m][3]);
            *(float4*)(C + (size_t)gr * N + bn + tc * 4) = v;
        }
    }
}

// ---------------- GCN layer pieces ----------------
// self_init: g_bufB[i,c] = g_bufA[i,c] * dis[i]^2 + bias[c]  (self-loop + bias seed)
__global__ void self_init(const float* __restrict__ bias) {
    size_t i = (size_t)blockIdx.x * blockDim.x + threadIdx.x;
    if (i >= (size_t)N_NODES * HID) return;
    int row = (int)(i >> 8);
    int col = (int)(i & 255);
    float d = g_dis[row];
    g_bufB[i] = fmaf(g_bufA[i], d * d, bias[col]);
}

// scatter: one warp per edge. g_bufB[dst] += g_bufA[src] * dis[src]*dis[dst]
__global__ void scatter_edges() {
    int w = (blockIdx.x * blockDim.x + threadIdx.x) >> 5;
    int lane = threadIdx.x & 31;
    if (w >= N_EDGES) return;
    int s = g_src[w];
    int d = g_dst[w];
    float norm = g_dis[s] * g_dis[d];
    const float4* hs = (const float4*)(g_bufA + (size_t)s * HID);
    float* ad = g_bufB + (size_t)d * HID;
#pragma unroll
    for (int j = 0; j < 2; j++) {
        int c4 = lane + j * 32;           // 64 float4 per 256-wide row
        float4 v = hs[c4];
        atomicAdd(ad + c4 * 4 + 0, v.x * norm);
        atomicAdd(ad + c4 * 4 + 1, v.y * norm);
        atomicAdd(ad + c4 * 4 + 2, v.z * norm);
        atomicAdd(ad + c4 * 4 + 3, v.w * norm);
    }
}

__global__ void relu_bufB() {
    size_t i = (size_t)blockIdx.x * blockDim.x + threadIdx.x;
    if (i < (size_t)N_NODES * HID) g_bufB[i] = fmaxf(g_bufB[i], 0.f);
}

// ---------------- pooling ----------------
__global__ void pool_sum() {
    size_t i = (size_t)blockIdx.x * blockDim.x + threadIdx.x;
    if (i >= (size_t)N_NODES * HID) return;
    int row = (int)(i >> 8);
    int col = (int)(i & 255);
    atomicAdd(&g_pool[g_batch[row] * HID + col], g_bufB[i]);
}

__global__ void pool_cnt() {
    int i = blockIdx.x * blockDim.x + threadIdx.x;
    if (i < N_NODES) atomicAdd(&g_cnt[g_batch[i]], 1.f);
}

__global__ void pool_div() {
    int i = blockIdx.x * blockDim.x + threadIdx.x;
    if (i < N_GRAPHS * HID) g_pool[i] /= fmaxf(g_cnt[i >> 8], 1.f);
}

// ---------------- fused MLP head: out[g] = relu(pool@Wm1+bm1) @ Wm2 + bm2 ----------------
__global__ void mlp_head(const float* __restrict__ Wm1, const float* __restrict__ bm1,
                         const float* __restrict__ Wm2, const float* __restrict__ bm2,
                         float* __restrict__ out) {
    int g = blockIdx.x;
    int c = threadIdx.x;          // 256 threads
    __shared__ float p[HID];
    __shared__ float z[HID];
    p[c] = g_pool[g * HID + c];
    __syncthreads();
    float acc = bm1[c];
#pragma unroll 8
    for (int k = 0; k < HID; k++) acc = fmaf(p[k], Wm1[k * HID + c], acc);
    z[c] = fmaxf(acc, 0.f) * Wm2[c];   // N_CLASSES == 1
    __syncthreads();
    for (int s = 128; s > 0; s >>= 1) {
        if (c < s) z[c] += z[c + s];
        __syncthreads();
    }
    if (c == 0) out[g] = z[0] + bm2[0];
}

// ---------------- launcher ----------------
extern "C" void kernel_launch(void* const* d_in, const int* in_sizes, int n_in,
                              void* d_out, int out_size) {
    const float* x   = (const float*)d_in[0];
    const void*  ei  = d_in[1];
    const void*  bt  = d_in[2];
    const float* W0  = (const float*)d_in[3];
    const float* b0  = (const float*)d_in[4];
    const float* W1  = (const float*)d_in[5];
    const float* b1  = (const float*)d_in[6];
    const float* W2  = (const float*)d_in[7];
    const float* b2  = (const float*)d_in[8];
    const float* Wm1 = (const float*)d_in[9];
    const float* bm1 = (const float*)d_in[10];
    const float* Wm2 = (const float*)d_in[11];
    const float* bm2 = (const float*)d_in[12];
    float* out = (float*)d_out;

    const size_t NH = (size_t)N_NODES * HID;
    const int nh_blocks = (int)((NH + 255) / 256);

    // normalize index dtypes (int32 vs int64) into int32 scratch
    detect_dtype<<<1, 32>>>((const unsigned int*)ei);
    convert_edges<<<(N_EDGES + 255) / 256, 256>>>(ei);
    convert_batch<<<(N_NODES + 255) / 256, 256>>>(bt);

    // degree -> deg_inv_sqrt
    zero_dis<<<(N_NODES + 255) / 256, 256>>>();
    deg_count<<<(N_EDGES + 255) / 256, 256>>>();
    deg_fin<<<(N_NODES + 255) / 256, 256>>>();

    dim3 gemm_block(256);
    dim3 gemm_grid(HID / 64, (N_NODES + 127) / 128);
    int scat_blocks = (N_EDGES * 32) / 256;

    // ---- layer 0: x(50000x128) ----
    sgemm_kernel<false><<<gemm_grid, gemm_block>>>(x, W0, N_NODES, F_IN, HID);
    self_init<<<nh_blocks, 256>>>(b0);
    scatter_edges<<<scat_blocks, 256>>>();
    relu_bufB<<<nh_blocks, 256>>>();

    // ---- layer 1 ----
    sgemm_kernel<true><<<gemm_grid, gemm_block>>>(nullptr, W1, N_NODES, HID, HID);
    self_init<<<nh_blocks, 256>>>(b1);
    scatter_edges<<<scat_blocks, 256>>>();
    relu_bufB<<<nh_blocks, 256>>>();

    // ---- layer 2 ----
    sgemm_kernel<true><<<gemm_grid, gemm_block>>>(nullptr, W2, N_NODES, HID, HID);
    self_init<<<nh_blocks, 256>>>(b2);
    scatter_edges<<<scat_blocks, 256>>>();
    relu_bufB<<<nh_blocks, 256>>>();

    // ---- mean pool ----
    zero_pool<<<(N_GRAPHS * HID + 255) / 256, 256>>>();
    pool_sum<<<nh_blocks, 256>>>();
    pool_cnt<<<(N_NODES + 255) / 256, 256>>>();
    pool_div<<<(N_GRAPHS * HID + 255) / 256, 256>>>();

    // ---- MLP head ----
    mlp_head<<<N_GRAPHS, HID>>>(Wm1, bm1, Wm2, bm2, out);
}

// round 4
// speedup vs baseline: 2.7320x; 2.7320x over previous
#include <cuda_runtime.h>

#define N_NODES 50000
#define N_EDGES 800000
#define N_GRAPHS 512
#define F_IN 128
#define HID 256
#define SCAN_BS 1024
#define NBLK ((N_NODES + SCAN_BS - 1) / SCAN_BS)   // 49

// ---------------- scratch (device globals) ----------------
__device__ int   g_is64;
__device__ int   g_src[N_EDGES];
__device__ int   g_dst[N_EDGES];
__device__ int   g_batch[N_NODES];
__device__ int   g_deg[N_NODES];
__device__ int   g_fill[N_NODES];
__device__ int   g_rowptr[N_NODES + 1];
__device__ int   g_eidx[N_EDGES];
__device__ int   g_blksum[64];
__device__ int   g_blkoff[64];
__device__ float g_dis[N_NODES];
__device__ float g_bufA[(size_t)N_NODES * HID];     // hw (GEMM out)
__device__ float g_bufB[(size_t)N_NODES * HID];     // layer out
__device__ float g_pool[N_GRAPHS * HID];
__device__ float g_cnt[N_GRAPHS];

// ---------------- index dtype detection + normalization ----------------
__global__ void detect_dtype(const unsigned int* __restrict__ raw) {
    if (threadIdx.x == 0) {
        int all_zero = 1;
        for (int i = 0; i < 128; i++)
            if (raw[2 * i + 1] != 0u) { all_zero = 0; break; }
        g_is64 = all_zero;
    }
}

__global__ void convert_edges(const void* __restrict__ raw) {
    int i = blockIdx.x * blockDim.x + threadIdx.x;
    if (i >= N_EDGES) return;
    if (g_is64) {
        const long long* p = (const long long*)raw;
        g_src[i] = (int)p[i];
        g_dst[i] = (int)p[i + N_EDGES];
    } else {
        const int* p = (const int*)raw;
        g_src[i] = p[i];
        g_dst[i] = p[i + N_EDGES];
    }
}

__global__ void convert_batch(const void* __restrict__ raw) {
    int i = blockIdx.x * blockDim.x + threadIdx.x;
    if (i >= N_NODES) return;
    if (g_is64) g_batch[i] = (int)((const long long*)raw)[i];
    else        g_batch[i] = ((const int*)raw)[i];
}

// ---------------- CSR construction ----------------
__global__ void zero_deg_fill() {
    int i = blockIdx.x * blockDim.x + threadIdx.x;
    if (i < N_NODES) { g_deg[i] = 0; g_fill[i] = 0; }
}

__global__ void deg_hist() {
    int i = blockIdx.x * blockDim.x + threadIdx.x;
    if (i < N_EDGES) atomicAdd(&g_deg[g_dst[i]], 1);
}

__global__ void scan_blocks() {
    __shared__ int sh[SCAN_BS];
    int i = blockIdx.x * SCAN_BS + threadIdx.x;
    int v = (i < N_NODES) ? g_deg[i] : 0;
    sh[threadIdx.x] = v;
    __syncthreads();
    for (int off = 1; off < SCAN_BS; off <<= 1) {
        int t = (threadIdx.x >= off) ? sh[threadIdx.x - off] : 0;
        __syncthreads();
        sh[threadIdx.x] += t;
        __syncthreads();
    }
    if (i < N_NODES) g_rowptr[i] = sh[threadIdx.x] - v;     // block-local exclusive
    if (threadIdx.x == SCAN_BS - 1) g_blksum[blockIdx.x] = sh[threadIdx.x];
}

__global__ void scan_sums() {
    __shared__ int sh[64];
    int v = ((int)threadIdx.x < NBLK) ? g_blksum[threadIdx.x] : 0;
    sh[threadIdx.x] = v;
    __syncthreads();
    for (int off = 1; off < 64; off <<= 1) {
        int t = (threadIdx.x >= off) ? sh[threadIdx.x - off] : 0;
        __syncthreads();
        sh[threadIdx.x] += t;
        __syncthreads();
    }
    if ((int)threadIdx.x < NBLK) g_blkoff[threadIdx.x] = sh[threadIdx.x] - v;
    if (threadIdx.x == 0) g_rowptr[N_NODES] = N_EDGES;
}

__global__ void scan_add() {
    int i = blockIdx.x * SCAN_BS + threadIdx.x;
    if (i < N_NODES) g_rowptr[i] += g_blkoff[blockIdx.x];
}

__global__ void deg_fin() {
    int i = blockIdx.x * blockDim.x + threadIdx.x;
    if (i < N_NODES) g_dis[i] = rsqrtf((float)g_deg[i] + 1.f);
}

__global__ void csr_fill() {
    int e = blockIdx.x * blockDim.x + threadIdx.x;
    if (e >= N_EDGES) return;
    int d = g_dst[e];
    int pos = g_rowptr[d] + atomicAdd(&g_fill[d], 1);
    g_eidx[pos] = g_src[e];
}

// ---------------- fp32 GEMM: g_bufA[M,256] = A[M,K] @ W[K,256] ----------------
// 128x128 block, BK=8, 256 threads, 8x8 microtile.
template <bool FROM_BUF>
__global__ void sgemm128(const float* __restrict__ Aext, const float* __restrict__ W,
                         int M, int K) {
    const int BM = 128, BK = 8;
    __shared__ float As[BK][BM + 4];
    __shared__ float Bs[BK][128];

    const float* A = FROM_BUF ? (const float*)g_bufB : Aext;
    float* C = g_bufA;

    int bm = blockIdx.y * BM;
    int bn = blockIdx.x * 128;
    int tid = threadIdx.x;
    int tr = tid >> 4;      // 0..15
    int tc = tid & 15;      // 0..15

    float acc[8][8];
#pragma unroll
    for (int m = 0; m < 8; m++)
#pragma unroll
        for (int n = 0; n < 8; n++) acc[m][n] = 0.f;

    for (int k0 = 0; k0 < K; k0 += BK) {
        // A tile: thread loads one float4: row = tid>>1, kq = (tid&1)*4
        {
            int r = tid >> 1, kq = (tid & 1) * 4;
            int gr = bm + r;
            float4 v = make_float4(0.f, 0.f, 0.f, 0.f);
            if (gr < M) v = *(const float4*)(A + (size_t)gr * K + k0 + kq);
            As[kq + 0][r] = v.x;
            As[kq + 1][r] = v.y;
            As[kq + 2][r] = v.z;
            As[kq + 3][r] = v.w;
        }
        // B tile: k = tid>>5, n4 = tid&31
        {
            int k = tid >> 5, n4 = tid & 31;
            *(float4*)&Bs[k][n4 * 4] =
                *(const float4*)(W + (size_t)(k0 + k) * HID + bn + n4 * 4);
        }
        __syncthreads();

#pragma unroll
        for (int k = 0; k < BK; k++) {
            float a[8], b[8];
            *(float4*)&a[0] = *(float4*)&As[k][tr * 8];
            *(float4*)&a[4] = *(float4*)&As[k][tr * 8 + 4];
            *(float4*)&b[0] = *(float4*)&Bs[k][tc * 8];
            *(float4*)&b[4] = *(float4*)&Bs[k][tc * 8 + 4];
#pragma unroll
            for (int m = 0; m < 8; m++)
#pragma unroll
                for (int n = 0; n < 8; n++) acc[m][n] = fmaf(a[m], b[n], acc[m][n]);
        }
        __syncthreads();
    }

#pragma unroll
    for (int m = 0; m < 8; m++) {
        int gr = bm + tr * 8 + m;
        if (gr < M) {
            *(float4*)(C + (size_t)gr * HID + bn + tc * 8)     =
                make_float4(acc[m][0], acc[m][1], acc[m][2], acc[m][3]);
            *(float4*)(C + (size_t)gr * HID + bn + tc * 8 + 4) =
                make_float4(acc[m][4], acc[m][5], acc[m][6], acc[m][7]);
        }
    }
}

// ---------------- fused GCN aggregate: warp per node ----------------
// out[i] = relu( bias + hw[i]*dis[i]^2 + sum_{s in N(i)} hw[s]*dis[s]*dis[i] )
// POOL: instead of writing bufB, atomicAdd relu'd result into g_pool[batch[i]].
template <bool POOL>
__global__ void gcn_gather(const float* __restrict__ bias) {
    int node = (blockIdx.x * blockDim.x + threadIdx.x) >> 5;
    int lane = threadIdx.x & 31;
    if (node >= N_NODES) return;

    float di = g_dis[node];
    float dd = di * di;
    const float4* hw = (const float4*)(g_bufA + (size_t)node * HID);
    const float4* bi = (const float4*)bias;

    float4 a0 = hw[lane], a1 = hw[lane + 32];
    float4 b0 = bi[lane], b1 = bi[lane + 32];
    a0.x = fmaf(a0.x, dd, b0.x); a0.y = fmaf(a0.y, dd, b0.y);
    a0.z = fmaf(a0.z, dd, b0.z); a0.w = fmaf(a0.w, dd, b0.w);
    a1.x = fmaf(a1.x, dd, b1.x); a1.y = fmaf(a1.y, dd, b1.y);
    a1.z = fmaf(a1.z, dd, b1.z); a1.w = fmaf(a1.w, dd, b1.w);

    int beg = g_rowptr[node], end = g_rowptr[node + 1];
    for (int e = beg; e < end; e++) {
        int s = g_eidx[e];
        float nrm = g_dis[s] * di;
        const float4* hs = (const float4*)(g_bufA + (size_t)s * HID);
        float4 v0 = hs[lane], v1 = hs[lane + 32];
        a0.x = fmaf(v0.x, nrm, a0.x); a0.y = fmaf(v0.y, nrm, a0.y);
        a0.z = fmaf(v0.z, nrm, a0.z); a0.w = fmaf(v0.w, nrm, a0.w);
        a1.x = fmaf(v1.x, nrm, a1.x); a1.y = fmaf(v1.y, nrm, a1.y);
        a1.z = fmaf(v1.z, nrm, a1.z); a1.w = fmaf(v1.w, nrm, a1.w);
    }

    a0.x = fmaxf(a0.x, 0.f); a0.y = fmaxf(a0.y, 0.f);
    a0.z = fmaxf(a0.z, 0.f); a0.w = fmaxf(a0.w, 0.f);
    a1.x = fmaxf(a1.x, 0.f); a1.y = fmaxf(a1.y, 0.f);
    a1.z = fmaxf(a1.z, 0.f); a1.w = fmaxf(a1.w, 0.f);

    if (POOL) {
        float* pp = g_pool + g_batch[node] * HID;
        atomicAdd(pp + lane * 4 + 0, a0.x);
        atomicAdd(pp + lane * 4 + 1, a0.y);
        atomicAdd(pp + lane * 4 + 2, a0.z);
        atomicAdd(pp + lane * 4 + 3, a0.w);
        atomicAdd(pp + 128 + lane * 4 + 0, a1.x);
        atomicAdd(pp + 128 + lane * 4 + 1, a1.y);
        atomicAdd(pp + 128 + lane * 4 + 2, a1.z);
        atomicAdd(pp + 128 + lane * 4 + 3, a1.w);
    } else {
        float4* ob = (float4*)(g_bufB + (size_t)node * HID);
        ob[lane] = a0;
        ob[lane + 32] = a1;
    }
}

// ---------------- pooling tail ----------------
__global__ void zero_pool() {
    int i = blockIdx.x * blockDim.x + threadIdx.x;
    if (i < N_GRAPHS * HID) g_pool[i] = 0.f;
    if (i < N_GRAPHS) g_cnt[i] = 0.f;
}

__global__ void pool_cnt() {
    int i = blockIdx.x * blockDim.x + threadIdx.x;
    if (i < N_NODES) atomicAdd(&g_cnt[g_batch[i]], 1.f);
}

__global__ void pool_div() {
    int i = blockIdx.x * blockDim.x + threadIdx.x;
    if (i < N_GRAPHS * HID) g_pool[i] /= fmaxf(g_cnt[i >> 8], 1.f);
}

// ---------------- fused MLP head ----------------
__global__ void mlp_head(const float* __restrict__ Wm1, const float* __restrict__ bm1,
                         const float* __restrict__ Wm2, const float* __restrict__ bm2,
                         float* __restrict__ out) {
    int g = blockIdx.x;
    int c = threadIdx.x;
    __shared__ float p[HID];
    __shared__ float z[HID];
    p[c] = g_pool[g * HID + c];
    __syncthreads();
    float acc = bm1[c];
#pragma unroll 8
    for (int k = 0; k < HID; k++) acc = fmaf(p[k], Wm1[k * HID + c], acc);
    z[c] = fmaxf(acc, 0.f) * Wm2[c];
    __syncthreads();
    for (int s = 128; s > 0; s >>= 1) {
        if (c < s) z[c] += z[c + s];
        __syncthreads();
    }
    if (c == 0) out[g] = z[0] + bm2[0];
}

// ---------------- launcher ----------------
extern "C" void kernel_launch(void* const* d_in, const int* in_sizes, int n_in,
                              void* d_out, int out_size) {
    const float* x   = (const float*)d_in[0];
    const void*  ei  = d_in[1];
    const void*  bt  = d_in[2];
    const float* W0  = (const float*)d_in[3];
    const float* b0  = (const float*)d_in[4];
    const float* W1  = (const float*)d_in[5];
    const float* b1  = (const float*)d_in[6];
    const float* W2  = (const float*)d_in[7];
    const float* b2  = (const float*)d_in[8];
    const float* Wm1 = (const float*)d_in[9];
    const float* bm1 = (const float*)d_in[10];
    const float* Wm2 = (const float*)d_in[11];
    const float* bm2 = (const float*)d_in[12];
    float* out = (float*)d_out;

    const int nb_nodes = (N_NODES + 255) / 256;
    const int nb_edges = (N_EDGES + 255) / 256;

    // index normalization
    detect_dtype<<<1, 32>>>((const unsigned int*)ei);
    convert_edges<<<nb_edges, 256>>>(ei);
    convert_batch<<<nb_nodes, 256>>>(bt);

    // CSR build + deg_inv_sqrt
    zero_deg_fill<<<nb_nodes, 256>>>();
    deg_hist<<<nb_edges, 256>>>();
    scan_blocks<<<NBLK, SCAN_BS>>>();
    scan_sums<<<1, 64>>>();
    scan_add<<<NBLK, SCAN_BS>>>();
    deg_fin<<<nb_nodes, 256>>>();
    csr_fill<<<nb_edges, 256>>>();

    dim3 gemm_grid(2, (N_NODES + 127) / 128);
    const int gat_blocks = (N_NODES * 32 + 255) / 256;

    // layer 0
    sgemm128<false><<<gemm_grid, 256>>>(x, W0, N_NODES, F_IN);
    gcn_gather<false><<<gat_blocks, 256>>>(b0);
    // layer 1
    sgemm128<true><<<gemm_grid, 256>>>(nullptr, W1, N_NODES, HID);
    gcn_gather<false><<<gat_blocks, 256>>>(b1);
    // layer 2 (+ fused pooling)
    sgemm128<true><<<gemm_grid, 256>>>(nullptr, W2, N_NODES, HID);
    zero_pool<<<(N_GRAPHS * HID + 255) / 256, 256>>>();
    pool_cnt<<<nb_nodes, 256>>>();
    gcn_gather<true><<<gat_blocks, 256>>>(b2);
    pool_div<<<(N_GRAPHS * HID + 255) / 256, 256>>>();

    // MLP head
    mlp_head<<<N_GRAPHS, HID>>>(Wm1, bm1, Wm2, bm2, out);
}